// round 3
// baseline (speedup 1.0000x reference)
#include <cuda_runtime.h>
#include <cuda_bf16.h>
#include <cstdint>

#define BATCH 256
#define EMBED 512
#define NCLS 100000
#define NSUB 3
#define NSROWS (NCLS*NSUB)

#define MT 128      // M rows per CTA
#define NT 96       // subcenter rows per CTA (= 32 classes)
#define KC 64       // K chunk
#define SROW 72     // padded smem row stride (bf16 elems)
#define THREADS 256
#define EPI_STRIDE 49

#define COSM 0.8775825618903728f
#define SINM 0.479425538604203f
#define THv (-0.8775825618903728f)
#define MMc 0.2397127693021015f
#define SCALE 64.0f

#define AS_BYTES (2*MT*SROW*2)
#define BS_BYTES (2*NT*SROW*2)
#define SMEM_BYTES (AS_BYTES + BS_BYTES + NT*4)

__device__ __nv_bfloat16 g_ebf[BATCH*EMBED];
__device__ float g_sumexp[BATCH];
__device__ float g_lablogit[BATCH];
__device__ float g_expadj[BATCH];

// fast exp via FMA-pipe polynomial (avoid MUFU.EX2 throughput wall)
__device__ __forceinline__ float fexp(float x){
    float y = x * 1.4426950408889634f;
    int   n = __float2int_rn(y);
    float f = y - (float)n;
    float p = fmaf(f, 1.3333558e-3f, 9.6181291e-3f);
    p = fmaf(f, p, 5.5504109e-2f);
    p = fmaf(f, p, 2.4022651e-1f);
    p = fmaf(f, p, 6.9314718e-1f);
    p = fmaf(f, p, 1.0f);
    return p * __int_as_float((n + 127) << 23);
}

// kernel 1: L2-normalize embeddings -> bf16 scratch; zero accumulators
__global__ void prep_kernel(const float* __restrict__ emb){
    int row = blockIdx.x;
    int t = threadIdx.x;
    float4 v = reinterpret_cast<const float4*>(emb + (size_t)row*EMBED)[t];
    float ss = v.x*v.x + v.y*v.y + v.z*v.z + v.w*v.w;
    #pragma unroll
    for (int o=16;o;o>>=1) ss += __shfl_xor_sync(0xffffffffu, ss, o);
    __shared__ float wss[4];
    if ((t & 31) == 0) wss[t>>5] = ss;
    __syncthreads();
    float tot = wss[0]+wss[1]+wss[2]+wss[3];
    float inv = 1.0f / fmaxf(sqrtf(tot), 1e-12f);
    __nv_bfloat162 p0 = __float22bfloat162_rn(make_float2(v.x*inv, v.y*inv));
    __nv_bfloat162 p1 = __float22bfloat162_rn(make_float2(v.z*inv, v.w*inv));
    uint2 u;
    u.x = *reinterpret_cast<uint32_t*>(&p0);
    u.y = *reinterpret_cast<uint32_t*>(&p1);
    reinterpret_cast<uint2*>(g_ebf + (size_t)row*EMBED)[t] = u;
    if (t == 0) g_sumexp[row] = 0.0f;
}

// kernel 1b: exact fp32 label logits + sumexp correction. One warp per row.
// Auto-detects int32 vs int64 label buffer.
__global__ void label_fix(const float* __restrict__ emb,
                          const float* __restrict__ W,
                          const void*  __restrict__ labels_raw){
    int row  = blockIdx.x*8 + (threadIdx.x >> 5);
    int lane = threadIdx.x & 31;

    const long long* l64 = (const long long*)labels_raw;
    const int*       l32 = (const int*)labels_raw;
    bool is64 = true;
    #pragma unroll
    for (int i=0;i<8;i++){
        long long v = l64[i];
        if (v < 0 || v >= (long long)NCLS) is64 = false;
    }
    long long lab = is64 ? l64[row] : (long long)l32[row];

    const float* e  = emb + (size_t)row*EMBED;
    const float* w0 = W   + (size_t)lab*NSUB*EMBED;

    float ess = 0.0f;
    float dot0=0.f, dot1=0.f, dot2=0.f;
    float ws0=0.f, ws1=0.f, ws2=0.f;
    for (int k = lane; k < EMBED; k += 32){
        float ev = e[k];
        ess = fmaf(ev, ev, ess);
        float a = w0[k];
        float b = w0[EMBED + k];
        float c = w0[2*EMBED + k];
        dot0 = fmaf(ev, a, dot0); ws0 = fmaf(a, a, ws0);
        dot1 = fmaf(ev, b, dot1); ws1 = fmaf(b, b, ws1);
        dot2 = fmaf(ev, c, dot2); ws2 = fmaf(c, c, ws2);
    }
    #pragma unroll
    for (int o=16;o;o>>=1){
        ess  += __shfl_xor_sync(0xffffffffu, ess,  o);
        dot0 += __shfl_xor_sync(0xffffffffu, dot0, o);
        dot1 += __shfl_xor_sync(0xffffffffu, dot1, o);
        dot2 += __shfl_xor_sync(0xffffffffu, dot2, o);
        ws0  += __shfl_xor_sync(0xffffffffu, ws0,  o);
        ws1  += __shfl_xor_sync(0xffffffffu, ws1,  o);
        ws2  += __shfl_xor_sync(0xffffffffu, ws2,  o);
    }
    if (lane == 0){
        float einv = 1.0f / fmaxf(sqrtf(ess), 1e-12f);
        float c0 = dot0 * einv / fmaxf(sqrtf(ws0), 1e-12f);
        float c1 = dot1 * einv / fmaxf(sqrtf(ws1), 1e-12f);
        float c2 = dot2 * einv / fmaxf(sqrtf(ws2), 1e-12f);
        float cs = fmaxf(c0, fmaxf(c1, c2));
        float sine = sqrtf(fmaxf(1.0f - cs*cs, 0.0f));
        float phi = (cs > THv) ? (cs*COSM - sine*SINM) : (cs - MMc);
        float ll = SCALE * phi;
        g_lablogit[row] = ll;
        // GEMM path adds exp(SCALE*cs) (no margin); swap it for exp(SCALE*phi)
        g_expadj[row] = fexp(ll) - fexp(SCALE * cs);
    }
}

// kernel 2: tiled GEMM + fused w-norm + subcenter-max + partial sumexp (no labels)
__global__ void __launch_bounds__(THREADS)
arc_main(const float* __restrict__ W){
    extern __shared__ char smem[];
    __nv_bfloat16* As = reinterpret_cast<__nv_bfloat16*>(smem);
    __nv_bfloat16* Bs = reinterpret_cast<__nv_bfloat16*>(smem + AS_BYTES);
    float* s_sum = reinterpret_cast<float*>(smem + AS_BYTES + BS_BYTES);
    float* epi = reinterpret_cast<float*>(smem);

    const int tid  = threadIdx.x;
    const int lane = tid & 31, warp = tid >> 5;
    const int g = lane >> 2, tg = lane & 3;
    const int wm = warp & 3, wn = warp >> 2;

    const int n0 = blockIdx.x * NT;
    const int m0 = blockIdx.y * MT;

    float acc[2][6][4];
    #pragma unroll
    for (int a=0;a<2;a++)
      #pragma unroll
      for (int b=0;b<6;b++)
        #pragma unroll
        for (int c=0;c<4;c++) acc[a][b][c] = 0.0f;
    float bsq[6] = {0,0,0,0,0,0};

    uint4  aR[4];
    float4 bR[6];

    const __nv_bfloat16* Aptr = g_ebf + (size_t)m0 * EMBED;

    auto loadA = [&](int k0){
        #pragma unroll
        for (int p=0;p<4;p++){
            int idx = p*THREADS + tid;
            int r = idx >> 3, q = idx & 7;
            aR[p] = *reinterpret_cast<const uint4*>(Aptr + (size_t)r*EMBED + k0 + q*8);
        }
    };
    auto loadB = [&](int k0){
        #pragma unroll
        for (int p=0;p<6;p++){
            int r = p*16 + (tid>>4);
            int c = (tid & 15) * 4;
            bR[p] = *reinterpret_cast<const float4*>(W + (size_t)(n0 + r)*EMBED + k0 + c);
        }
    };
    auto storeA = [&](int buf){
        #pragma unroll
        for (int p=0;p<4;p++){
            int idx = p*THREADS + tid;
            int r = idx >> 3, q = idx & 7;
            *reinterpret_cast<uint4*>(As + (size_t)(buf*MT + r)*SROW + q*8) = aR[p];
        }
    };
    auto storeB = [&](int buf){
        #pragma unroll
        for (int p=0;p<6;p++){
            int r = p*16 + (tid>>4);
            int c = (tid & 15) * 4;
            float4 v = bR[p];
            bsq[p] = fmaf(v.x,v.x, fmaf(v.y,v.y, fmaf(v.z,v.z, fmaf(v.w,v.w, bsq[p]))));
            __nv_bfloat162 lo = __float22bfloat162_rn(make_float2(v.x, v.y));
            __nv_bfloat162 hi = __float22bfloat162_rn(make_float2(v.z, v.w));
            uint2 u;
            u.x = *reinterpret_cast<uint32_t*>(&lo);
            u.y = *reinterpret_cast<uint32_t*>(&hi);
            *reinterpret_cast<uint2*>(Bs + (size_t)(buf*NT + r)*SROW + c) = u;
        }
    };
    auto mmachunk = [&](int buf){
        const __nv_bfloat16* Ab = As + (size_t)buf*MT*SROW;
        const __nv_bfloat16* Bb = Bs + (size_t)buf*NT*SROW;
        #pragma unroll
        for (int kk=0; kk<4; kk++){
            int kb = kk*16;
            uint32_t af[2][4];
            uint32_t bf[6][2];
            #pragma unroll
            for (int mt=0; mt<2; mt++){
                int r = wm*32 + mt*16;
                af[mt][0] = *reinterpret_cast<const uint32_t*>(Ab + (r+g  )*SROW + kb + 2*tg);
                af[mt][1] = *reinterpret_cast<const uint32_t*>(Ab + (r+g+8)*SROW + kb + 2*tg);
                af[mt][2] = *reinterpret_cast<const uint32_t*>(Ab + (r+g  )*SROW + kb + 2*tg + 8);
                af[mt][3] = *reinterpret_cast<const uint32_t*>(Ab + (r+g+8)*SROW + kb + 2*tg + 8);
            }
            #pragma unroll
            for (int nt=0; nt<6; nt++){
                int n = wn*48 + nt*8 + g;
                bf[nt][0] = *reinterpret_cast<const uint32_t*>(Bb + n*SROW + kb + 2*tg);
                bf[nt][1] = *reinterpret_cast<const uint32_t*>(Bb + n*SROW + kb + 2*tg + 8);
            }
            #pragma unroll
            for (int mt=0; mt<2; mt++)
                #pragma unroll
                for (int nt=0; nt<6; nt++){
                    float* d = acc[mt][nt];
                    asm volatile(
                      "mma.sync.aligned.m16n8k16.row.col.f32.bf16.bf16.f32 "
                      "{%0,%1,%2,%3}, {%4,%5,%6,%7}, {%8,%9}, {%0,%1,%2,%3};\n"
                      : "+f"(d[0]), "+f"(d[1]), "+f"(d[2]), "+f"(d[3])
                      : "r"(af[mt][0]), "r"(af[mt][1]), "r"(af[mt][2]), "r"(af[mt][3]),
                        "r"(bf[nt][0]), "r"(bf[nt][1]));
                }
        }
    };

    loadA(0); loadB(0);
    storeA(0); storeB(0);
    __syncthreads();

    #pragma unroll
    for (int kc=0; kc<8; kc++){
        if (kc < 7){ loadA((kc+1)*KC); loadB((kc+1)*KC); }
        mmachunk(kc & 1);
        if (kc < 7){
            storeA((kc+1) & 1); storeB((kc+1) & 1);
            __syncthreads();
        }
    }

    // per-row ||w||^2 reduction (16 threads per row)
    #pragma unroll
    for (int p=0;p<6;p++){
        float v = bsq[p];
        #pragma unroll
        for (int o=8;o;o>>=1) v += __shfl_xor_sync(0xffffffffu, v, o, 16);
        if ((lane & 15) == 0) s_sum[p*16 + (tid>>4)] = v;
    }
    __syncthreads();
    if (tid < NT) s_sum[tid] = rsqrtf(fmaxf(s_sum[tid], 1e-24f));
    __syncthreads();

    // scale by 1/||w|| and stage warp tile (32 rows x 48 cols) in smem
    float* my_epi = epi + (size_t)warp * (32 * EPI_STRIDE);
    #pragma unroll
    for (int mt=0; mt<2; mt++)
        #pragma unroll
        for (int nt=0; nt<6; nt++){
            int c0 = wn*48 + nt*8 + 2*tg;
            float i0 = s_sum[c0], i1 = s_sum[c0+1];
            int r0 = mt*16 + g;
            int cc = nt*8 + 2*tg;
            my_epi[ r0     *EPI_STRIDE + cc    ] = acc[mt][nt][0]*i0;
            my_epi[ r0     *EPI_STRIDE + cc + 1] = acc[mt][nt][1]*i1;
            my_epi[(r0 + 8)*EPI_STRIDE + cc    ] = acc[mt][nt][2]*i0;
            my_epi[(r0 + 8)*EPI_STRIDE + cc + 1] = acc[mt][nt][3]*i1;
        }
    __syncwarp();

    // each lane owns one row: 16 classes -> max3, partial sumexp (no margin here)
    const int grow = m0 + wm*32 + lane;
    float partial = 0.0f;
    #pragma unroll
    for (int c=0;c<16;c++){
        float v0 = my_epi[lane*EPI_STRIDE + c*3    ];
        float v1 = my_epi[lane*EPI_STRIDE + c*3 + 1];
        float v2 = my_epi[lane*EPI_STRIDE + c*3 + 2];
        float cs = fmaxf(v0, fmaxf(v1, v2));
        partial += fexp(SCALE * cs);
    }
    atomicAdd(&g_sumexp[grow], partial);
}

// kernel 3: mean over rows of (log(sumexp_corrected) - label_logit)
__global__ void finalize_kernel(float* __restrict__ out){
    int t = threadIdx.x;  // 256
    float S = g_sumexp[t] + g_expadj[t];
    float v = logf(S) - g_lablogit[t];
    #pragma unroll
    for (int o=16;o;o>>=1) v += __shfl_xor_sync(0xffffffffu, v, o);
    __shared__ float ws[8];
    if ((t & 31) == 0) ws[t>>5] = v;
    __syncthreads();
    if (t == 0){
        float s = 0.0f;
        #pragma unroll
        for (int i=0;i<8;i++) s += ws[i];
        out[0] = s * (1.0f/256.0f);
    }
}

extern "C" void kernel_launch(void* const* d_in, const int* in_sizes, int n_in,
                              void* d_out, int out_size){
    int ie = 0, il = 1, iw = 2;
    for (int i = 0; i < n_in; i++){
        if (in_sizes[i] == BATCH) il = i;
        else if (in_sizes[i] == BATCH*EMBED) ie = i;
        else if (in_sizes[i] == NSROWS*EMBED) iw = i;
    }
    const float* emb    = (const float*)d_in[ie];
    const void*  labels = (const void*)d_in[il];
    const float* W      = (const float*)d_in[iw];

    cudaFuncSetAttribute(arc_main, cudaFuncAttributeMaxDynamicSharedMemorySize, SMEM_BYTES);

    prep_kernel<<<BATCH, 128>>>(emb);
    label_fix<<<BATCH/8, 256>>>(emb, W, labels);
    dim3 grid(NCLS/32, BATCH/MT);
    arc_main<<<grid, THREADS, SMEM_BYTES>>>(W);
    finalize_kernel<<<1, 256>>>((float*)d_out);
}

// round 4
// speedup vs baseline: 2.3250x; 2.3250x over previous
#include <cuda_runtime.h>
#include <cuda_bf16.h>
#include <cstdint>

#define BATCH 256
#define EMBED 512
#define NCLS 100000
#define NSUB 3
#define NSROWS (NCLS*NSUB)

#define MT 256      // all batch rows per CTA -> W streamed exactly once
#define NT 96       // subcenter rows per CTA (= 32 classes)
#define KC 64       // K chunk
#define STAGES 3
#define SROW 72     // A smem row stride (bf16 elems): 144B, LDSM conflict-free
#define SROWB 72    // B smem row stride (fp32 words): 288B, LDS.64 conflict-free
#define THREADS 256
#define EPI_STRIDE 49

#define COSM 0.8775825618903728f
#define SINM 0.479425538604203f
#define THv (-0.8775825618903728f)
#define MMc 0.2397127693021015f
#define SCALE 64.0f

#define A_STAGE_BYTES (MT*SROW*2)        // 36864
#define B_STAGE_BYTES (NT*SROWB*4)       // 27648
#define STAGE_BYTES   (A_STAGE_BYTES + B_STAGE_BYTES)
#define PIPE_BYTES    (STAGES*STAGE_BYTES)           // 193536
#define SMEM_BYTES    (PIPE_BYTES + NT*4)            // + s_sum

__device__ __nv_bfloat16 g_ebf[BATCH*EMBED];
__device__ float g_sumexp[BATCH];
__device__ float g_lablogit[BATCH];
__device__ float g_expadj[BATCH];

// fast exp via FMA-pipe polynomial (avoid MUFU.EX2 throughput wall)
__device__ __forceinline__ float fexp(float x){
    float y = x * 1.4426950408889634f;
    int   n = __float2int_rn(y);
    float f = y - (float)n;
    float p = fmaf(f, 1.3333558e-3f, 9.6181291e-3f);
    p = fmaf(f, p, 5.5504109e-2f);
    p = fmaf(f, p, 2.4022651e-1f);
    p = fmaf(f, p, 6.9314718e-1f);
    p = fmaf(f, p, 1.0f);
    return p * __int_as_float((n + 127) << 23);
}

__device__ __forceinline__ uint32_t smem_u32(const void* p){
    return (uint32_t)__cvta_generic_to_shared(p);
}

// kernel 1: L2-normalize embeddings -> bf16 scratch; zero accumulators
__global__ void prep_kernel(const float* __restrict__ emb){
    int row = blockIdx.x;
    int t = threadIdx.x;
    float4 v = reinterpret_cast<const float4*>(emb + (size_t)row*EMBED)[t];
    float ss = v.x*v.x + v.y*v.y + v.z*v.z + v.w*v.w;
    #pragma unroll
    for (int o=16;o;o>>=1) ss += __shfl_xor_sync(0xffffffffu, ss, o);
    __shared__ float wss[4];
    if ((t & 31) == 0) wss[t>>5] = ss;
    __syncthreads();
    float tot = wss[0]+wss[1]+wss[2]+wss[3];
    float inv = 1.0f / fmaxf(sqrtf(tot), 1e-12f);
    __nv_bfloat162 p0 = __float22bfloat162_rn(make_float2(v.x*inv, v.y*inv));
    __nv_bfloat162 p1 = __float22bfloat162_rn(make_float2(v.z*inv, v.w*inv));
    uint2 u;
    u.x = *reinterpret_cast<uint32_t*>(&p0);
    u.y = *reinterpret_cast<uint32_t*>(&p1);
    reinterpret_cast<uint2*>(g_ebf + (size_t)row*EMBED)[t] = u;
    if (t == 0) g_sumexp[row] = 0.0f;
}

// kernel 1b: exact fp32 label logits + sumexp correction. One warp per row.
__global__ void label_fix(const float* __restrict__ emb,
                          const float* __restrict__ W,
                          const void*  __restrict__ labels_raw){
    int row  = blockIdx.x*8 + (threadIdx.x >> 5);
    int lane = threadIdx.x & 31;

    const long long* l64 = (const long long*)labels_raw;
    const int*       l32 = (const int*)labels_raw;
    bool is64 = true;
    #pragma unroll
    for (int i=0;i<8;i++){
        long long v = l64[i];
        if (v < 0 || v >= (long long)NCLS) is64 = false;
    }
    long long lab = is64 ? l64[row] : (long long)l32[row];

    const float* e  = emb + (size_t)row*EMBED;
    const float* w0 = W   + (size_t)lab*NSUB*EMBED;

    float ess = 0.0f;
    float dot0=0.f, dot1=0.f, dot2=0.f;
    float ws0=0.f, ws1=0.f, ws2=0.f;
    for (int k = lane; k < EMBED; k += 32){
        float ev = e[k];
        ess = fmaf(ev, ev, ess);
        float a = w0[k];
        float b = w0[EMBED + k];
        float c = w0[2*EMBED + k];
        dot0 = fmaf(ev, a, dot0); ws0 = fmaf(a, a, ws0);
        dot1 = fmaf(ev, b, dot1); ws1 = fmaf(b, b, ws1);
        dot2 = fmaf(ev, c, dot2); ws2 = fmaf(c, c, ws2);
    }
    #pragma unroll
    for (int o=16;o;o>>=1){
        ess  += __shfl_xor_sync(0xffffffffu, ess,  o);
        dot0 += __shfl_xor_sync(0xffffffffu, dot0, o);
        dot1 += __shfl_xor_sync(0xffffffffu, dot1, o);
        dot2 += __shfl_xor_sync(0xffffffffu, dot2, o);
        ws0  += __shfl_xor_sync(0xffffffffu, ws0,  o);
        ws1  += __shfl_xor_sync(0xffffffffu, ws1,  o);
        ws2  += __shfl_xor_sync(0xffffffffu, ws2,  o);
    }
    if (lane == 0){
        float einv = 1.0f / fmaxf(sqrtf(ess), 1e-12f);
        float c0 = dot0 * einv / fmaxf(sqrtf(ws0), 1e-12f);
        float c1 = dot1 * einv / fmaxf(sqrtf(ws1), 1e-12f);
        float c2 = dot2 * einv / fmaxf(sqrtf(ws2), 1e-12f);
        float cs = fmaxf(c0, fmaxf(c1, c2));
        float sine = sqrtf(fmaxf(1.0f - cs*cs, 0.0f));
        float phi = (cs > THv) ? (cs*COSM - sine*SINM) : (cs - MMc);
        float ll = SCALE * phi;
        g_lablogit[row] = ll;
        g_expadj[row] = fexp(ll) - fexp(SCALE * cs);
    }
}

// kernel 2: cp.async-pipelined GEMM + fused w-norm + subcenter-max + partial sumexp
__global__ void __launch_bounds__(THREADS, 1)
arc_main(const float* __restrict__ W){
    extern __shared__ char smem[];
    float* s_sum = reinterpret_cast<float*>(smem + PIPE_BYTES);
    float* epi   = reinterpret_cast<float*>(smem);   // reuse pipeline smem after loop

    const int tid  = threadIdx.x;
    const int lane = tid & 31, warp = tid >> 5;
    const int g = lane >> 2, tg = lane & 3;
    const int wm = warp & 3, wn = warp >> 2;     // 4 M-warps x 2 N-warps, tile 64x48

    const int n0 = blockIdx.x * NT;

    float acc[4][6][4];
    #pragma unroll
    for (int a=0;a<4;a++)
      #pragma unroll
      for (int b=0;b<6;b++)
        #pragma unroll
        for (int c=0;c<4;c++) acc[a][b][c] = 0.0f;
    float bsq[6] = {0,0,0,0,0,0};

    const uint32_t smem_base = smem_u32(smem);

    // issue cp.async for chunk (k0) into stage buf
    auto issue = [&](int k0, int buf){
        uint32_t a_dst = smem_base + buf*STAGE_BYTES;
        uint32_t b_dst = smem_base + buf*STAGE_BYTES + A_STAGE_BYTES;
        const __nv_bfloat16* a_src = g_ebf + k0;
        const float*         b_src = W + (size_t)n0*EMBED + k0;
        #pragma unroll
        for (int p=0;p<8;p++){                 // A: 256 rows x 128B
            int idx = p*THREADS + tid;
            int r = idx >> 3, q = idx & 7;
            uint32_t d = a_dst + (uint32_t)(r*(SROW*2) + q*16);
            const void* s = a_src + (size_t)r*EMBED + q*8;
            asm volatile("cp.async.cg.shared.global [%0], [%1], 16;\n" :: "r"(d), "l"(s));
        }
        #pragma unroll
        for (int p=0;p<6;p++){                 // B: 96 rows x 256B (fp32)
            int idx = p*THREADS + tid;
            int r = idx >> 4, q = idx & 15;
            uint32_t d = b_dst + (uint32_t)(r*(SROWB*4) + q*16);
            const void* s = b_src + (size_t)r*EMBED + q*4;
            asm volatile("cp.async.cg.shared.global [%0], [%1], 16;\n" :: "r"(d), "l"(s));
        }
        asm volatile("cp.async.commit_group;\n");
    };

    auto mmachunk = [&](int buf){
        const __nv_bfloat16* Ab = reinterpret_cast<const __nv_bfloat16*>(smem + buf*STAGE_BYTES);
        const float*         Bb = reinterpret_cast<const float*>(smem + buf*STAGE_BYTES + A_STAGE_BYTES);
        #pragma unroll
        for (int kk=0; kk<4; kk++){
            const int kb = kk*16;
            uint32_t af[4][4];
            #pragma unroll
            for (int mt=0; mt<4; mt++){
                int r = wm*64 + mt*16 + (lane & 15);
                uint32_t addr = smem_u32(Ab + r*SROW + kb + (lane >> 4)*8);
                asm volatile("ldmatrix.sync.aligned.m8n8.x4.shared.b16 {%0,%1,%2,%3}, [%4];\n"
                             : "=r"(af[mt][0]), "=r"(af[mt][1]), "=r"(af[mt][2]), "=r"(af[mt][3])
                             : "r"(addr));
            }
            uint32_t bfr[6][2];
            #pragma unroll
            for (int nt=0; nt<6; nt++){
                int n = wn*48 + nt*8 + g;
                const float* bp = Bb + n*SROWB + kb + 2*tg;
                float2 v0 = *reinterpret_cast<const float2*>(bp);
                float2 v1 = *reinterpret_cast<const float2*>(bp + 8);
                if (wm == 0)
                    bsq[nt] += fmaf(v0.x,v0.x, fmaf(v0.y,v0.y, fmaf(v1.x,v1.x, v1.y*v1.y)));
                asm volatile("cvt.rn.bf16x2.f32 %0, %1, %2;\n" : "=r"(bfr[nt][0]) : "f"(v0.y), "f"(v0.x));
                asm volatile("cvt.rn.bf16x2.f32 %0, %1, %2;\n" : "=r"(bfr[nt][1]) : "f"(v1.y), "f"(v1.x));
            }
            #pragma unroll
            for (int mt=0; mt<4; mt++)
                #pragma unroll
                for (int nt=0; nt<6; nt++){
                    float* d = acc[mt][nt];
                    asm volatile(
                      "mma.sync.aligned.m16n8k16.row.col.f32.bf16.bf16.f32 "
                      "{%0,%1,%2,%3}, {%4,%5,%6,%7}, {%8,%9}, {%0,%1,%2,%3};\n"
                      : "+f"(d[0]), "+f"(d[1]), "+f"(d[2]), "+f"(d[3])
                      : "r"(af[mt][0]), "r"(af[mt][1]), "r"(af[mt][2]), "r"(af[mt][3]),
                        "r"(bfr[nt][0]), "r"(bfr[nt][1]));
                }
        }
    };

    // prologue: chunks 0, 1 in flight
    issue(0, 0);
    issue(KC, 1);

    #pragma unroll 1
    for (int kc=0; kc<8; kc++){
        if (kc < 7) asm volatile("cp.async.wait_group 1;\n");
        else        asm volatile("cp.async.wait_group 0;\n");
        __syncthreads();                       // chunk kc ready; prior stage reads done
        if (kc + 2 < 8) issue((kc+2)*KC, (kc+2)%STAGES);
        mmachunk(kc % STAGES);
    }

    // per-row ||w||^2: wm==0 warps hold full partials; reduce over tg group of 4
    if (wm == 0){
        #pragma unroll
        for (int nt=0; nt<6; nt++){
            float v = bsq[nt];
            v += __shfl_xor_sync(0xffffffffu, v, 1);
            v += __shfl_xor_sync(0xffffffffu, v, 2);
            if (tg == 0) s_sum[wn*48 + nt*8 + g] = v;
        }
    }
    __syncthreads();
    if (tid < NT) s_sum[tid] = rsqrtf(fmaxf(s_sum[tid], 1e-24f));
    __syncthreads();   // all MMA/smem reads done; safe to reuse pipe smem as epi

    // scale by 1/||w|| and stage warp tile (64 rows x 48 cols) in smem
    float* my_epi = epi + (size_t)warp * (64 * EPI_STRIDE);
    #pragma unroll
    for (int mt=0; mt<4; mt++)
        #pragma unroll
        for (int nt=0; nt<6; nt++){
            int c0 = wn*48 + nt*8 + 2*tg;
            float i0 = s_sum[c0], i1 = s_sum[c0+1];
            int r0 = mt*16 + g;
            int cc = nt*8 + 2*tg;
            my_epi[ r0     *EPI_STRIDE + cc    ] = acc[mt][nt][0]*i0;
            my_epi[ r0     *EPI_STRIDE + cc + 1] = acc[mt][nt][1]*i1;
            my_epi[(r0 + 8)*EPI_STRIDE + cc    ] = acc[mt][nt][2]*i0;
            my_epi[(r0 + 8)*EPI_STRIDE + cc + 1] = acc[mt][nt][3]*i1;
        }
    __syncwarp();

    // each lane owns rows lane and lane+32 of the warp tile: max3 + sumexp
    #pragma unroll
    for (int h=0; h<2; h++){
        int rr = lane + h*32;
        float partial = 0.0f;
        #pragma unroll
        for (int c=0; c<16; c++){
            float v0 = my_epi[rr*EPI_STRIDE + c*3    ];
            float v1 = my_epi[rr*EPI_STRIDE + c*3 + 1];
            float v2 = my_epi[rr*EPI_STRIDE + c*3 + 2];
            float cs = fmaxf(v0, fmaxf(v1, v2));
            partial += fexp(SCALE * cs);
        }
        atomicAdd(&g_sumexp[wm*64 + rr], partial);
    }
}

// kernel 3: mean over rows of (log(sumexp_corrected) - label_logit)
__global__ void finalize_kernel(float* __restrict__ out){
    int t = threadIdx.x;  // 256
    float S = g_sumexp[t] + g_expadj[t];
    float v = logf(S) - g_lablogit[t];
    #pragma unroll
    for (int o=16;o;o>>=1) v += __shfl_xor_sync(0xffffffffu, v, o);
    __shared__ float ws[8];
    if ((t & 31) == 0) ws[t>>5] = v;
    __syncthreads();
    if (t == 0){
        float s = 0.0f;
        #pragma unroll
        for (int i=0;i<8;i++) s += ws[i];
        out[0] = s * (1.0f/256.0f);
    }
}

extern "C" void kernel_launch(void* const* d_in, const int* in_sizes, int n_in,
                              void* d_out, int out_size){
    int ie = 0, il = 1, iw = 2;
    for (int i = 0; i < n_in; i++){
        if (in_sizes[i] == BATCH) il = i;
        else if (in_sizes[i] == BATCH*EMBED) ie = i;
        else if (in_sizes[i] == NSROWS*EMBED) iw = i;
    }
    const float* emb    = (const float*)d_in[ie];
    const void*  labels = (const void*)d_in[il];
    const float* W      = (const float*)d_in[iw];

    cudaFuncSetAttribute(arc_main, cudaFuncAttributeMaxDynamicSharedMemorySize, SMEM_BYTES);

    prep_kernel<<<BATCH, 128>>>(emb);
    label_fix<<<BATCH/8, 256>>>(emb, W, labels);
    dim3 grid(NCLS/32, 1);   // 3125 CTAs, W streamed once
    arc_main<<<grid, THREADS, SMEM_BYTES>>>(W);
    finalize_kernel<<<1, 256>>>((float*)d_out);
}